// round 4
// baseline (speedup 1.0000x reference)
#include <cuda_runtime.h>
#include <cstdint>

// Problem constants
#define Bc   8
#define Tc   256
#define Uc   64
#define Dc   640
#define Vc   1024
#define K2c  1280
#define MOUT (Bc*Tc*Uc)     // 131072 output rows

__device__ __forceinline__ uint32_t f2tf(float x) {
    uint32_t r;
    asm("cvt.rna.tf32.f32 %0, %1;" : "=r"(r) : "f"(x));
    return r;
}

// 59 KB dynamic shared memory per block (3 blocks/SM -> 177 KB)
struct __align__(16) Smem {
    float P[64][128];                                   // 32 KB, persists to store phase
    union {
        struct { uint32_t As[64][36]; uint32_t Bs[128][36]; } g;  // 27.0 KB gemm staging
        float E[32][128];                               // 16 KB store-phase slab
    } u;
};

// ---------------------------------------------------------------------------
// ONE fused kernel. grid = (V/128 = 8, 4*B = 32), 256 threads, 3 blocks/SM.
//   Block (bx, by): b = by>>2, t0 = (by&3)*64, v-cols [bx*128, +128)
// Phase P: cP[64 u x 128 v] = ReLU(pred) @ Wp^T -> smem P (+bias)
// Phase E: cE[64 t x 128 v] = ReLU(enc)  @ We^T  (same registers, reused)
// Phase C: expand in 2 slabs of 32 t: out = E[t][v] + P[u][v]  (2 MB/block)
// ---------------------------------------------------------------------------
__global__ __launch_bounds__(256, 3) void fused_joiner(
    const float* __restrict__ enc,
    const float* __restrict__ pred,
    const float* __restrict__ W,
    const float* __restrict__ bias,
    float4* __restrict__ out,
    const int* __restrict__ slen,
    const int* __restrict__ tlen,
    int writeTail)
{
    extern __shared__ char smem_raw[];
    Smem& sm = *reinterpret_cast<Smem*>(smem_raw);

    const int tid  = threadIdx.x;
    const int warp = tid >> 5;
    const int lane = tid & 31;
    const int g    = lane >> 2;     // 0..7
    const int q    = lane & 3;      // 0..3
    const int bn0  = blockIdx.x * 128;          // v-col offset
    const int b    = blockIdx.y >> 2;
    const int bt0  = b * Tc + (blockIdx.y & 3) * 64;

    const int lr = tid >> 3;        // 0..31
    const int lc = (tid & 7) * 4;   // 0,4..28
    const int mg = warp & 3;        // m-group: 16 rows each (64 total)
    const int ng = warp >> 2;       // n-group: 64 cols each (128 total)

    float c[8][4];
    float4 ra[2], rw[4];

    // ===================== Phase P: 64 x 128 =====================
#pragma unroll
    for (int nt = 0; nt < 8; nt++)
#pragma unroll
        for (int r = 0; r < 4; r++) c[nt][r] = 0.f;

#pragma unroll
    for (int i = 0; i < 2; i++)
        ra[i] = *(const float4*)&pred[(size_t)(b * Uc + lr + i * 32) * Dc + lc];
#pragma unroll
    for (int i = 0; i < 4; i++)
        rw[i] = *(const float4*)&W[(size_t)(bn0 + lr + i * 32) * K2c + Dc + lc];

    for (int k0 = 0; k0 < Dc; k0 += 32) {
#pragma unroll
        for (int i = 0; i < 2; i++) {
            int row = lr + i * 32;
            sm.u.g.As[row][lc+0] = f2tf(fmaxf(ra[i].x, 0.f));
            sm.u.g.As[row][lc+1] = f2tf(fmaxf(ra[i].y, 0.f));
            sm.u.g.As[row][lc+2] = f2tf(fmaxf(ra[i].z, 0.f));
            sm.u.g.As[row][lc+3] = f2tf(fmaxf(ra[i].w, 0.f));
        }
#pragma unroll
        for (int i = 0; i < 4; i++) {
            int row = lr + i * 32;
            sm.u.g.Bs[row][lc+0] = f2tf(rw[i].x);
            sm.u.g.Bs[row][lc+1] = f2tf(rw[i].y);
            sm.u.g.Bs[row][lc+2] = f2tf(rw[i].z);
            sm.u.g.Bs[row][lc+3] = f2tf(rw[i].w);
        }
        __syncthreads();
        if (k0 + 32 < Dc) {
#pragma unroll
            for (int i = 0; i < 2; i++)
                ra[i] = *(const float4*)&pred[(size_t)(b * Uc + lr + i * 32) * Dc + k0 + 32 + lc];
#pragma unroll
            for (int i = 0; i < 4; i++)
                rw[i] = *(const float4*)&W[(size_t)(bn0 + lr + i * 32) * K2c + Dc + k0 + 32 + lc];
        }
#pragma unroll
        for (int kk = 0; kk < 4; kk++) {
            uint32_t af[4];
            af[0] = sm.u.g.As[mg*16 + g    ][kk*8 + q    ];
            af[1] = sm.u.g.As[mg*16 + g + 8][kk*8 + q    ];
            af[2] = sm.u.g.As[mg*16 + g    ][kk*8 + q + 4];
            af[3] = sm.u.g.As[mg*16 + g + 8][kk*8 + q + 4];
#pragma unroll
            for (int nt = 0; nt < 8; nt++) {
                int n = ng*64 + nt*8 + g;
                uint32_t b0 = sm.u.g.Bs[n][kk*8 + q];
                uint32_t b1 = sm.u.g.Bs[n][kk*8 + q + 4];
                asm volatile(
                    "mma.sync.aligned.m16n8k8.row.col.f32.tf32.tf32.f32 "
                    "{%0,%1,%2,%3}, {%4,%5,%6,%7}, {%8,%9}, {%0,%1,%2,%3};\n"
                    : "+f"(c[nt][0]), "+f"(c[nt][1]), "+f"(c[nt][2]), "+f"(c[nt][3])
                    : "r"(af[0]), "r"(af[1]), "r"(af[2]), "r"(af[3]),
                      "r"(b0), "r"(b1));
            }
        }
        __syncthreads();
    }

    // dump P (+bias) to persistent smem region, freeing the accumulators
    {
        int r0 = mg * 16 + g;
#pragma unroll
        for (int nt = 0; nt < 8; nt++) {
            int col = ng*64 + nt*8 + q*2;
            float b0 = bias[bn0 + col];
            float b1 = bias[bn0 + col + 1];
            sm.P[r0    ][col    ] = c[nt][0] + b0;
            sm.P[r0    ][col + 1] = c[nt][1] + b1;
            sm.P[r0 + 8][col    ] = c[nt][2] + b0;
            sm.P[r0 + 8][col + 1] = c[nt][3] + b1;
        }
    }

    // ===================== Phase E: 64 x 128 (same registers) ==============
#pragma unroll
    for (int nt = 0; nt < 8; nt++)
#pragma unroll
        for (int r = 0; r < 4; r++) c[nt][r] = 0.f;

#pragma unroll
    for (int i = 0; i < 2; i++)
        ra[i] = *(const float4*)&enc[(size_t)(bt0 + lr + i * 32) * Dc + lc];
#pragma unroll
    for (int i = 0; i < 4; i++)
        rw[i] = *(const float4*)&W[(size_t)(bn0 + lr + i * 32) * K2c + lc];

    // NOTE: staging writes below are safe — previous loop ended on __syncthreads()
    for (int k0 = 0; k0 < Dc; k0 += 32) {
#pragma unroll
        for (int i = 0; i < 2; i++) {
            int row = lr + i * 32;
            sm.u.g.As[row][lc+0] = f2tf(fmaxf(ra[i].x, 0.f));
            sm.u.g.As[row][lc+1] = f2tf(fmaxf(ra[i].y, 0.f));
            sm.u.g.As[row][lc+2] = f2tf(fmaxf(ra[i].z, 0.f));
            sm.u.g.As[row][lc+3] = f2tf(fmaxf(ra[i].w, 0.f));
        }
#pragma unroll
        for (int i = 0; i < 4; i++) {
            int row = lr + i * 32;
            sm.u.g.Bs[row][lc+0] = f2tf(rw[i].x);
            sm.u.g.Bs[row][lc+1] = f2tf(rw[i].y);
            sm.u.g.Bs[row][lc+2] = f2tf(rw[i].z);
            sm.u.g.Bs[row][lc+3] = f2tf(rw[i].w);
        }
        __syncthreads();
        if (k0 + 32 < Dc) {
#pragma unroll
            for (int i = 0; i < 2; i++)
                ra[i] = *(const float4*)&enc[(size_t)(bt0 + lr + i * 32) * Dc + k0 + 32 + lc];
#pragma unroll
            for (int i = 0; i < 4; i++)
                rw[i] = *(const float4*)&W[(size_t)(bn0 + lr + i * 32) * K2c + k0 + 32 + lc];
        }
#pragma unroll
        for (int kk = 0; kk < 4; kk++) {
            uint32_t af[4];
            af[0] = sm.u.g.As[mg*16 + g    ][kk*8 + q    ];
            af[1] = sm.u.g.As[mg*16 + g + 8][kk*8 + q    ];
            af[2] = sm.u.g.As[mg*16 + g    ][kk*8 + q + 4];
            af[3] = sm.u.g.As[mg*16 + g + 8][kk*8 + q + 4];
#pragma unroll
            for (int nt = 0; nt < 8; nt++) {
                int n = ng*64 + nt*8 + g;
                uint32_t b0 = sm.u.g.Bs[n][kk*8 + q];
                uint32_t b1 = sm.u.g.Bs[n][kk*8 + q + 4];
                asm volatile(
                    "mma.sync.aligned.m16n8k8.row.col.f32.tf32.tf32.f32 "
                    "{%0,%1,%2,%3}, {%4,%5,%6,%7}, {%8,%9}, {%0,%1,%2,%3};\n"
                    : "+f"(c[nt][0]), "+f"(c[nt][1]), "+f"(c[nt][2]), "+f"(c[nt][3])
                    : "r"(af[0]), "r"(af[1]), "r"(af[2]), "r"(af[3]),
                      "r"(b0), "r"(b1));
            }
        }
        __syncthreads();
    }

    // ===================== Phase C: expand (2 slabs of 32 t) ===============
    const int vq = lane;  // float4 column within the 128-col v-tile
#pragma unroll 1
    for (int s = 0; s < 2; s++) {
        // warps whose m-rows fall in slab s write accumulators into sm.u.E
        if ((mg >> 1) == s) {
            int r0 = (mg & 1) * 16 + g;   // local row within 32-row slab
#pragma unroll
            for (int nt = 0; nt < 8; nt++) {
                int col = ng*64 + nt*8 + q*2;
                sm.u.E[r0    ][col    ] = c[nt][0];
                sm.u.E[r0    ][col + 1] = c[nt][1];
                sm.u.E[r0 + 8][col    ] = c[nt][2];
                sm.u.E[r0 + 8][col + 1] = c[nt][3];
            }
        }
        __syncthreads();

        float4 e[4];
        size_t obase[4];
#pragma unroll
        for (int ti = 0; ti < 4; ti++) {
            int tl = warp * 4 + ti;                    // local t row in slab
            e[ti] = ((const float4*)sm.u.E[tl])[vq];
            int trow = bt0 + s * 32 + tl;              // global bt row
            obase[ti] = (size_t)trow * Uc * 256 + blockIdx.x * 32 + vq;
        }
#pragma unroll 4
        for (int u = 0; u < Uc; u++) {
            float4 p = ((const float4*)sm.P[u])[vq];
#pragma unroll
            for (int ti = 0; ti < 4; ti++) {
                float4 r;
                r.x = e[ti].x + p.x; r.y = e[ti].y + p.y;
                r.z = e[ti].z + p.z; r.w = e[ti].w + p.w;
                out[obase[ti] + (size_t)u * 256] = r;
            }
        }
        __syncthreads();
    }

    // passthrough lengths appended after the joint output
    if (writeTail && blockIdx.x == 0 && blockIdx.y == 0 && tid < 16) {
        float* o = (float*)out;
        size_t tb = (size_t)MOUT * Vc;
        if (tid < 8) o[tb + tid] = (float)slen[tid];
        else         o[tb + tid] = (float)tlen[tid - 8];
    }
}

extern "C" void kernel_launch(void* const* d_in, const int* in_sizes, int n_in,
                              void* d_out, int out_size)
{
    const float* enc  = (const float*)d_in[0];  // [B,T,D]
    const int*   slen = (const int*)  d_in[1];  // [B]
    const float* pred = (const float*)d_in[2];  // [B,U,D]
    const int*   tlen = (const int*)  d_in[3];  // [B]
    const float* W    = (const float*)d_in[4];  // [V, 2D]
    const float* bias = (const float*)d_in[5];  // [V]
    float* out = (float*)d_out;

    int smemBytes = (int)sizeof(Smem);
    cudaFuncSetAttribute(fused_joiner,
                         cudaFuncAttributeMaxDynamicSharedMemorySize, smemBytes);

    int writeTail = (out_size >= (int)((size_t)MOUT * Vc + 16)) ? 1 : 0;
    fused_joiner<<<dim3(Vc / 128, 4 * Bc), 256, smemBytes>>>(
        enc, pred, W, bias, (float4*)out, slen, tlen, writeTail);
}